// round 2
// baseline (speedup 1.0000x reference)
#include <cuda_runtime.h>
#include <math.h>

#define E_N 200000
#define P_N 50000
#define D_N 128
#define C_N 32

// ---------------- scratch (static __device__ globals; no allocs) ----------------
__device__ __align__(16) float g_esb[2][(size_t)E_N * D_N];  // 2 x 102.4 MB (ping-pong)
__device__ __align__(16) float g_psb[2][(size_t)P_N * D_N];  // 2 x  25.6 MB (ping-pong)
__device__ __align__(16) float g_emsg[(size_t)E_N * D_N];    // 102.4 MB
__device__ __align__(16) float g_pmsg[(size_t)P_N * D_N];    //  25.6 MB
__device__ __align__(16) float g_W[4][512 * 256];            // packed GRU weights
__device__ __align__(16) float g_b[4][512];                  // packed GRU biases
__device__ __align__(16) float g_seedsum[D_N];

// ---------------- input staging ----------------
__global__ void copy_in_kernel(const float4* __restrict__ es, const float4* __restrict__ ps) {
    int t = blockIdx.x * blockDim.x + threadIdx.x;
    const int ne = E_N * 32, np = P_N * 32;
    if (t < ne)            ((float4*)g_esb[0])[t]      = es[t];
    else if (t < ne + np)  ((float4*)g_psb[0])[t - ne] = ps[t - ne];
}

// zero both msg buffers + seed accumulator (run once per layer, before spmm/seedsum)
__global__ void zero_msg_kernel() {
    int t = blockIdx.x * blockDim.x + threadIdx.x;
    const int ne = E_N * 32, np = P_N * 32;
    float4 z = make_float4(0.f, 0.f, 0.f, 0.f);
    if (t < ne)            ((float4*)g_emsg)[t]      = z;
    else if (t < ne + np)  ((float4*)g_pmsg)[t - ne] = z;
    if (t < D_N) g_seedsum[t] = 0.f;
}

// ---------------- weight packing ----------------
// Wcat rows: [0,256): [Wih_j | Whh_j]  (r,z gate sums)
//            [256,384): [Wih_j | 0]    (xn)   -> only k<128 is nonzero
//            [384,512): [0 | Whh_{j-128}] (hn)-> only k>=128 is nonzero
__global__ void pack_kernel(const float* __restrict__ Wih, const float* __restrict__ Whh,
                            const float* __restrict__ bih, const float* __restrict__ bhh, int g) {
    int t = blockIdx.x * blockDim.x + threadIdx.x;
    if (t < 512 * 256) {
        int j = t >> 8, k = t & 255;
        float v;
        if (j < 256)       v = (k < 128) ? Wih[j * 128 + k] : Whh[j * 128 + (k - 128)];
        else if (j < 384)  v = (k < 128) ? Wih[j * 128 + k] : 0.f;
        else               v = (k < 128) ? 0.f : Whh[(j - 128) * 128 + (k - 128)];
        g_W[g][t] = v;
        if (t < 512) {
            float b;
            if (t < 256)      b = bih[t] + bhh[t];
            else if (t < 384) b = bih[t];
            else              b = bhh[t - 128];
            g_b[g][t] = b;
        }
    }
}

// ---------------- seed sum (mean applied at use site via inv_nseed) ----------------
__global__ void seedsum_kernel(const int* __restrict__ seed, int es_src) {
    int d = threadIdx.x;                       // 128 threads
    int b = blockIdx.x;                        // one block per seed
    float v = g_esb[es_src][(size_t)seed[b] * D_N + d];
    atomicAdd(&g_seedsum[d], v);
}

// ---------------- SpMM (segment-sum) via vector reductions ----------------
// 8 threads per edge; each handles 4 float4 chunks of the 128-float row.
__global__ void spmm_kernel(const int* __restrict__ rows, const int* __restrict__ cols,
                            const float* __restrict__ vals, int nnz, int p_side, int src) {
    int t = blockIdx.x * blockDim.x + threadIdx.x;
    int eid = t >> 3;
    if (eid >= nnz) return;
    int sub = t & 7;
    int r = rows[eid];
    int c = cols[eid];
    float w = vals[eid];
    const float4* s4;
    float4* d4;
    if (p_side) { s4 = (const float4*)(g_esb[src] + (size_t)r * 128); d4 = (float4*)(g_pmsg + (size_t)c * 128); }
    else        { s4 = (const float4*)(g_psb[src] + (size_t)c * 128); d4 = (float4*)(g_emsg + (size_t)r * 128); }
#pragma unroll
    for (int q = 0; q < 4; q++) {
        float4 v = s4[sub + q * 8];
        v.x *= w; v.y *= w; v.z *= w; v.w *= w;
        float* addr = (float*)(d4 + sub + q * 8);
        asm volatile("red.global.add.v4.f32 [%0], {%1,%2,%3,%4};"
                     :: "l"(addr), "f"(v.x), "f"(v.y), "f"(v.z), "f"(v.w) : "memory");
    }
}

// ---------------- fused GEMM + GRU ----------------
// Computes all 512 gate pre-activations for 64 rows per block (BM=64, BN=512),
// then applies the GRU nonlinearity in registers and writes h' to the dst buffer.
// Zero-block skip: xn accumulates only k<128 (kt 0..7), hn only k>=128 (kt 8..15).
__device__ __forceinline__ void gtile(
    int kt0, int kt1, int nOff,
    float (&accR)[8][2], float (&accZ)[8][2], float (&accN)[8][2],
    const float* __restrict__ msg, const float* __restrict__ Hsrc,
    const float* __restrict__ Wp,
    float (*As)[64], float (*Bs)[512],
    int tid, int tr8, int d0, int rowBase, int M, int is_e, float inv)
{
    for (int kt = kt0; kt < kt1; kt++) {
        if (tid < 256) {
            int ar = tid >> 2;                 // 0..63 (row within block)
            int kq = (tid & 3) << 2;           // 0,4,8,12
            int gk = (kt << 4) + kq;           // 0..255
            int grow = rowBase + ar;
            float4 v = make_float4(0.f, 0.f, 0.f, 0.f);
            if (grow < M) {
                if (gk < 128) {
                    v = *(const float4*)(msg + (size_t)grow * 128 + gk);
                    if (is_e) {
                        float4 s = *(const float4*)(g_seedsum + gk);
                        v.x += s.x * inv; v.y += s.y * inv;
                        v.z += s.z * inv; v.w += s.w * inv;
                    }
                } else {
                    v = *(const float4*)(Hsrc + (size_t)grow * 128 + (gk - 128));
                }
            }
            As[kq + 0][ar] = v.x; As[kq + 1][ar] = v.y;
            As[kq + 2][ar] = v.z; As[kq + 3][ar] = v.w;
        }
        {
            // each thread stages W row n = tid (output col), 16 k-values
            const float4* wr = (const float4*)(Wp + ((size_t)tid << 8) + (kt << 4));
#pragma unroll
            for (int i = 0; i < 4; i++) {
                float4 wv = wr[i];
                Bs[i * 4 + 0][tid] = wv.x; Bs[i * 4 + 1][tid] = wv.y;
                Bs[i * 4 + 2][tid] = wv.z; Bs[i * 4 + 3][tid] = wv.w;
            }
        }
        __syncthreads();
#pragma unroll
        for (int kk = 0; kk < 16; kk++) {
            float a[8];
            *(float4*)(a)     = *(const float4*)&As[kk][tr8];
            *(float4*)(a + 4) = *(const float4*)&As[kk][tr8 + 4];
            float2 br = *(const float2*)&Bs[kk][d0];
            float2 bz = *(const float2*)&Bs[kk][128 + d0];
            float2 bn = *(const float2*)&Bs[kk][nOff + d0];
#pragma unroll
            for (int i = 0; i < 8; i++) {
                accR[i][0] += a[i] * br.x; accR[i][1] += a[i] * br.y;
                accZ[i][0] += a[i] * bz.x; accZ[i][1] += a[i] * bz.y;
                accN[i][0] += a[i] * bn.x; accN[i][1] += a[i] * bn.y;
            }
        }
        __syncthreads();
    }
}

__global__ __launch_bounds__(512, 1) void gemm_gru_kernel(int M, int g, int is_e,
                                                          int hsrc, int hdst, float inv) {
    const float* __restrict__ msg  = is_e ? g_emsg : g_pmsg;
    const float* __restrict__ Hsrc = is_e ? g_esb[hsrc] : g_psb[hsrc];
    float* __restrict__ Hdst       = is_e ? g_esb[hdst] : g_psb[hdst];
    const float* __restrict__ Wp   = g_W[g];

    __shared__ float As[16][64];    //  4 KB
    __shared__ float Bs[16][512];   // 32 KB

    const int tid = threadIdx.x;
    const int tr8 = (tid >> 6) << 3;     // row offset within block: 0,8,..,56
    const int d0  = (tid & 63) << 1;     // feature pair: 0,2,..,126
    const int rowBase = blockIdx.x * 64;

    float accR[8][2], accZ[8][2], accX[8][2], accH[8][2];
#pragma unroll
    for (int i = 0; i < 8; i++) {
        accR[i][0] = accR[i][1] = 0.f;
        accZ[i][0] = accZ[i][1] = 0.f;
        accX[i][0] = accX[i][1] = 0.f;
        accH[i][0] = accH[i][1] = 0.f;
    }

    // k < 128: r,z + xn;  k >= 128: r,z + hn
    gtile(0, 8, 256, accR, accZ, accX, msg, Hsrc, Wp, As, Bs,
          tid, tr8, d0, rowBase, M, is_e, inv);
    gtile(8, 16, 384, accR, accZ, accH, msg, Hsrc, Wp, As, Bs,
          tid, tr8, d0, rowBase, M, is_e, inv);

    const float* __restrict__ bias = g_b[g];
    const float bR0 = bias[d0],       bR1 = bias[d0 + 1];
    const float bZ0 = bias[128 + d0], bZ1 = bias[128 + d0 + 1];
    const float bX0 = bias[256 + d0], bX1 = bias[256 + d0 + 1];
    const float bH0 = bias[384 + d0], bH1 = bias[384 + d0 + 1];

#pragma unroll
    for (int i = 0; i < 8; i++) {
        int row = rowBase + tr8 + i;
        if (row < M) {
            float2 hv = *(const float2*)(Hsrc + (size_t)row * 128 + d0);
            float2 o;
            {
                float r = 1.f / (1.f + expf(-(accR[i][0] + bR0)));
                float z = 1.f / (1.f + expf(-(accZ[i][0] + bZ0)));
                float n = tanhf(accX[i][0] + bX0 + r * (accH[i][0] + bH0));
                o.x = (1.f - z) * n + z * hv.x;
            }
            {
                float r = 1.f / (1.f + expf(-(accR[i][1] + bR1)));
                float z = 1.f / (1.f + expf(-(accZ[i][1] + bZ1)));
                float n = tanhf(accX[i][1] + bX1 + r * (accH[i][1] + bH1));
                o.y = (1.f - z) * n + z * hv.y;
            }
            *(float2*)(Hdst + (size_t)row * 128 + d0) = o;
        }
    }
}

// ---------------- FC head: logits = es @ fc_w^T + fc_b ----------------
__global__ __launch_bounds__(256) void fc_kernel(const float* __restrict__ fc_w,
                                                 const float* __restrict__ fc_b,
                                                 float* __restrict__ out) {
    __shared__ float4 Wt[32 * 32];   // [k4][c], conflict-free
    __shared__ float4 xb[8][32];
    int tid = threadIdx.x;
    for (int t = tid; t < 4096; t += 256) {
        int c = t >> 7;
        int k = t & 127;
        ((float*)&Wt[(k >> 2) * 32 + c])[k & 3] = fc_w[t];
    }
    __syncthreads();
    int w = tid >> 5, lane = tid & 31;
    float bias = fc_b[lane];
    int gw = blockIdx.x * 8 + w;
    int nw = gridDim.x * 8;
    for (int row = gw; row < E_N; row += nw) {
        xb[w][lane] = ((const float4*)g_esb[0])[(size_t)row * 32 + lane];
        __syncwarp();
        float acc = bias;
#pragma unroll
        for (int k4 = 0; k4 < 32; k4++) {
            float4 x  = xb[w][k4];
            float4 wv = Wt[k4 * 32 + lane];
            acc += x.x * wv.x + x.y * wv.y + x.z * wv.z + x.w * wv.w;
        }
        out[(size_t)row * 32 + lane] = acc;
        __syncwarp();
    }
}

// ---------------- output staging ----------------
__global__ void copy_out_kernel(float4* __restrict__ oes, float4* __restrict__ ops) {
    int t = blockIdx.x * blockDim.x + threadIdx.x;
    const int ne = E_N * 32, np = P_N * 32;
    if (t < ne)            oes[t]      = ((const float4*)g_esb[0])[t];
    else if (t < ne + np)  ops[t - ne] = ((const float4*)g_psb[0])[t - ne];
}

// ---------------- launch ----------------
extern "C" void kernel_launch(void* const* d_in, const int* in_sizes, int n_in,
                              void* d_out, int out_size) {
    const int*   seed  = (const int*)d_in[0];
    const float* es_in = (const float*)d_in[1];
    const float* ps_in = (const float*)d_in[2];
    const int*   erow  = (const int*)d_in[3];
    const int*   ecol  = (const int*)d_in[4];
    const float* eval  = (const float*)d_in[5];
    const float* fc_w  = (const float*)d_in[22];
    const float* fc_b  = (const float*)d_in[23];
    float* out = (float*)d_out;
    const int nseed = in_sizes[0];
    const int nnz   = in_sizes[3];
    const float inv = 1.f / (float)nseed;

    const int copyThreads = (E_N + P_N) * 32;
    copy_in_kernel<<<(copyThreads + 255) / 256, 256>>>((const float4*)es_in, (const float4*)ps_in);

    for (int l = 0; l < 2; l++)
        for (int pe = 0; pe < 2; pe++) {
            int g = l * 2 + pe;                 // 0=l0_e 1=l0_p 2=l1_e 3=l1_p
            int base = 6 + l * 8 + pe * 4;
            pack_kernel<<<(512 * 256 + 255) / 256, 256>>>(
                (const float*)d_in[base], (const float*)d_in[base + 1],
                (const float*)d_in[base + 2], (const float*)d_in[base + 3], g);
        }

    for (int l = 0; l < 2; l++) {
        const int src = l;          // l0: read 0 write 1; l1: read 1 write 0 (final in 0)
        const int dst = 1 - l;
        zero_msg_kernel<<<(copyThreads + 255) / 256, 256>>>();
        seedsum_kernel<<<nseed, 128>>>(seed, src);      // seeds from pre-update es
        int spmmThreads = nnz * 8;
        // p_msg = segsum(es[rows]*w by cols); ps' = GRU(p_msg, ps)
        spmm_kernel<<<(spmmThreads + 255) / 256, 256>>>(erow, ecol, eval, nnz, 1, src);
        gemm_gru_kernel<<<(P_N + 63) / 64, 512>>>(P_N, l * 2 + 1, 0, src, dst, inv);
        // e_msg = segsum(ps'[cols]*w by rows) + seed_mean; es' = GRU(e_msg, es)
        spmm_kernel<<<(spmmThreads + 255) / 256, 256>>>(erow, ecol, eval, nnz, 0, dst);
        gemm_gru_kernel<<<(E_N + 63) / 64, 512>>>(E_N, l * 2, 1, src, dst, inv);
    }

    fc_kernel<<<592, 256>>>(fc_w, fc_b, out);
    copy_out_kernel<<<(copyThreads + 255) / 256, 256>>>(
        (float4*)(out + (size_t)E_N * C_N),
        (float4*)(out + (size_t)E_N * C_N + (size_t)E_N * D_N));
}

// round 3
// speedup vs baseline: 1.5294x; 1.5294x over previous
#include <cuda_runtime.h>
#include <math.h>
#include <stdint.h>

#define E_N 200000
#define P_N 50000
#define D_N 128
#define C_N 32

// ---------------- scratch (static __device__ globals; no allocs) ----------------
__device__ __align__(16) float    g_esb[2][(size_t)E_N * D_N];  // ping-pong h for entities
__device__ __align__(16) float    g_psb[2][(size_t)P_N * D_N];  // ping-pong h for pages
__device__ __align__(16) float    g_emsg[(size_t)E_N * D_N];
__device__ __align__(16) float    g_pmsg[(size_t)P_N * D_N];
__device__ __align__(16) uint32_t g_Wt[4][2 * 384 * 128];       // tf32: [gate][phase(ih/hh)][384][128]
__device__ __align__(16) float    g_b[4][512];                  // packed biases
__device__ __align__(16) float    g_seedsum[D_N];

__device__ __forceinline__ uint32_t f2tf32(float x) {
    uint32_t r;
    asm("cvt.rna.tf32.f32 %0, %1;" : "=r"(r) : "f"(x));
    return r;
}

__device__ __forceinline__ void mma_tf32(float* d, const uint32_t* a, const uint32_t* b) {
    asm volatile("mma.sync.aligned.m16n8k8.row.col.f32.tf32.tf32.f32 "
                 "{%0,%1,%2,%3}, {%4,%5,%6,%7}, {%8,%9}, {%0,%1,%2,%3};"
                 : "+f"(d[0]), "+f"(d[1]), "+f"(d[2]), "+f"(d[3])
                 : "r"(a[0]), "r"(a[1]), "r"(a[2]), "r"(a[3]), "r"(b[0]), "r"(b[1]));
}

// ---------------- input staging ----------------
__global__ void copy_in_kernel(const float4* __restrict__ es, const float4* __restrict__ ps) {
    int t = blockIdx.x * blockDim.x + threadIdx.x;
    const int ne = E_N * 32, np = P_N * 32;
    if (t < ne)            ((float4*)g_esb[0])[t]      = es[t];
    else if (t < ne + np)  ((float4*)g_psb[0])[t - ne] = ps[t - ne];
}

// zero both msg buffers + seed accumulator (per layer)
__global__ void zero_msg_kernel() {
    int t = blockIdx.x * blockDim.x + threadIdx.x;
    const int ne = E_N * 32, np = P_N * 32;
    float4 z = make_float4(0.f, 0.f, 0.f, 0.f);
    if (t < ne)            ((float4*)g_emsg)[t]      = z;
    else if (t < ne + np)  ((float4*)g_pmsg)[t - ne] = z;
    if (t < D_N) g_seedsum[t] = 0.f;
}

// ---------------- weight packing (tf32 conversion + bias combine) ----------------
// Phase 0 (k<128): B = Wih rows 0..383.  Phase 1 (k>=128): B = Whh rows 0..383.
// Gate cols: [0,128)=r, [128,256)=z, [256,384)=n. r/z accumulate both phases,
// xn only phase 0, hn only phase 1 — zero-blocks never materialize.
__global__ void pack_tc_kernel(const float* __restrict__ Wih, const float* __restrict__ Whh,
                               const float* __restrict__ bih, const float* __restrict__ bhh, int g) {
    int t = blockIdx.x * blockDim.x + threadIdx.x;
    const int half = 384 * 128;
    if (t < 2 * half) {
        const float* W = (t < half) ? Wih : Whh;
        g_Wt[g][t] = f2tf32(W[(t < half) ? t : (t - half)]);
    }
    if (t < 512) {
        float b;
        if (t < 256)      b = bih[t] + bhh[t];          // r, z sums
        else if (t < 384) b = bih[t];                    // xn
        else              b = bhh[t - 128];              // hn
        g_b[g][t] = b;
    }
}

// ---------------- seed sum (mean via inv_nseed at use site) ----------------
__global__ void seedsum_kernel(const int* __restrict__ seed, int es_src) {
    int d = threadIdx.x;                       // 128 threads
    int b = blockIdx.x;                        // one block per seed
    float v = g_esb[es_src][(size_t)seed[b] * D_N + d];
    atomicAdd(&g_seedsum[d], v);
}

// ---------------- SpMM (segment-sum) via vector reductions ----------------
__global__ void spmm_kernel(const int* __restrict__ rows, const int* __restrict__ cols,
                            const float* __restrict__ vals, int nnz, int p_side, int src) {
    int t = blockIdx.x * blockDim.x + threadIdx.x;
    int eid = t >> 3;
    if (eid >= nnz) return;
    int sub = t & 7;
    int r = rows[eid];
    int c = cols[eid];
    float w = vals[eid];
    const float4* s4;
    float4* d4;
    if (p_side) { s4 = (const float4*)(g_esb[src] + (size_t)r * 128); d4 = (float4*)(g_pmsg + (size_t)c * 128); }
    else        { s4 = (const float4*)(g_psb[src] + (size_t)c * 128); d4 = (float4*)(g_emsg + (size_t)r * 128); }
#pragma unroll
    for (int q = 0; q < 4; q++) {
        float4 v = s4[sub + q * 8];
        v.x *= w; v.y *= w; v.z *= w; v.w *= w;
        float* addr = (float*)(d4 + sub + q * 8);
        asm volatile("red.global.add.v4.f32 [%0], {%1,%2,%3,%4};"
                     :: "l"(addr), "f"(v.x), "f"(v.y), "f"(v.z), "f"(v.w) : "memory");
    }
}

// ---------------- tensor-core fused GEMM + GRU ----------------
// BM=64, BN=512 (all gates), 256 threads / 8 warps. Warp w covers 64 gate cols
// (colBase = w*64). Warps 0-3: r,z (both phases). Warps 4,5: xn (phase 0 only,
// packed slots 4,5). Warps 6,7: hn (phase 1 only, packed slots 4,5).
// Arena: As[2][64][20] tf32 | Bs[2][384][20] tf32; epilogue reuses it as
// gateS[32][520] in two 32-row passes.
#define ARENA_U32 17920   // 71680 bytes

__global__ __launch_bounds__(256, 1) void gemm_gru_tc(int M, int g, int is_e,
                                                      int hsrc, int hdst, float inv) {
    extern __shared__ uint32_t arena[];
    uint32_t* As = arena;                 // 2*64*20 = 2560
    uint32_t* Bs = arena + 2560;          // 2*384*20 = 15360
    float* gateS = (float*)arena;         // 32*520 = 16640 (reuse)

    const float* __restrict__ msg  = is_e ? g_emsg : g_pmsg;
    const float* __restrict__ Hsrc = is_e ? g_esb[hsrc] : g_psb[hsrc];
    float* __restrict__ Hdst       = is_e ? g_esb[hdst] : g_psb[hdst];
    const uint32_t* __restrict__ Wt = g_Wt[g];

    const int tid = threadIdx.x;
    const int w = tid >> 5, lane = tid & 31;
    const int gq = lane >> 2, tq = lane & 3;
    const int rowBase = blockIdx.x * 64;

    float acc[4][8][4];
#pragma unroll
    for (int mt = 0; mt < 4; mt++)
#pragma unroll
        for (int nt = 0; nt < 8; nt++)
#pragma unroll
            for (int q = 0; q < 4; q++) acc[mt][nt][q] = 0.f;

    auto stage = [&](int buf, int ks) {
        int phase = ks >> 3;
        // A tile: 64 rows x 16 k
        {
            int r = tid >> 2, kq = (tid & 3) << 2;
            int grow = rowBase + r;
            float4 v = make_float4(0.f, 0.f, 0.f, 0.f);
            if (grow < M) {
                int col = (ks & 7) * 16 + kq;
                if (phase == 0) {
                    v = *(const float4*)(msg + (size_t)grow * 128 + col);
                    if (is_e) {
                        float4 s = *(const float4*)(g_seedsum + col);
                        v.x += s.x * inv; v.y += s.y * inv;
                        v.z += s.z * inv; v.w += s.w * inv;
                    }
                } else {
                    v = *(const float4*)(Hsrc + (size_t)grow * 128 + col);
                }
            }
            uint32_t* dst = As + buf * 1280 + r * 20 + kq;
            dst[0] = f2tf32(v.x); dst[1] = f2tf32(v.y);
            dst[2] = f2tf32(v.z); dst[3] = f2tf32(v.w);
        }
        // B tile: 384 packed cols x 16 k (already tf32)
        const uint32_t* src = Wt + phase * 49152 + (ks & 7) * 16;
#pragma unroll
        for (int i = 0; i < 6; i++) {
            int fid = i * 256 + tid;
            int pn = fid >> 2, kq = (fid & 3) << 2;
            uint4 wv = *(const uint4*)(src + pn * 128 + kq);
            uint32_t* dst = Bs + buf * 7680 + pn * 20 + kq;
            dst[0] = wv.x; dst[1] = wv.y; dst[2] = wv.z; dst[3] = wv.w;
        }
    };

    stage(0, 0);
    __syncthreads();
    for (int ks = 0; ks < 16; ks++) {
        int cur = ks & 1;
        if (ks + 1 < 16) stage(cur ^ 1, ks + 1);
        int phase = ks >> 3;
        bool active; int slot;
        if (w < 4)            { active = true;      slot = w; }
        else if (phase == 0)  { active = (w < 6);   slot = w; }
        else                  { active = (w >= 6);  slot = w - 2; }
        if (active) {
            const uint32_t* Ab = As + cur * 1280;
            const uint32_t* Bb = Bs + cur * 7680 + slot * 64 * 20;
#pragma unroll
            for (int k8 = 0; k8 < 16; k8 += 8) {
                uint32_t af[4][4];
#pragma unroll
                for (int mt = 0; mt < 4; mt++) {
                    int m0 = mt * 16;
                    af[mt][0] = Ab[(m0 + gq) * 20 + k8 + tq];
                    af[mt][1] = Ab[(m0 + gq + 8) * 20 + k8 + tq];
                    af[mt][2] = Ab[(m0 + gq) * 20 + k8 + tq + 4];
                    af[mt][3] = Ab[(m0 + gq + 8) * 20 + k8 + tq + 4];
                }
#pragma unroll
                for (int nt = 0; nt < 8; nt++) {
                    uint32_t bf[2];
                    bf[0] = Bb[(nt * 8 + gq) * 20 + k8 + tq];
                    bf[1] = Bb[(nt * 8 + gq) * 20 + k8 + tq + 4];
#pragma unroll
                    for (int mt = 0; mt < 4; mt++)
                        mma_tf32(acc[mt][nt], af[mt], bf);
                }
            }
        }
        __syncthreads();
    }

    // ---------- fused GRU epilogue: two 32-row passes through smem ----------
    const float* __restrict__ bias = g_b[g];
    const int colBase = w * 64;
#pragma unroll
    for (int pass = 0; pass < 2; pass++) {
        if (pass) __syncthreads();   // pass0 protected by mainloop's final sync
#pragma unroll
        for (int mh = 0; mh < 2; mh++) {
            int mt = pass * 2 + mh;
            int rb = mh * 16;
#pragma unroll
            for (int nt = 0; nt < 8; nt++) {
                int col = colBase + nt * 8 + tq * 2;
                gateS[(rb + gq) * 520 + col]         = acc[mt][nt][0];
                gateS[(rb + gq) * 520 + col + 1]     = acc[mt][nt][1];
                gateS[(rb + gq + 8) * 520 + col]     = acc[mt][nt][2];
                gateS[(rb + gq + 8) * 520 + col + 1] = acc[mt][nt][3];
            }
        }
        __syncthreads();
#pragma unroll
        for (int i = 0; i < 16; i++) {
            int idx = tid + i * 256;
            int row = idx >> 7, d = idx & 127;
            int grow = rowBase + pass * 32 + row;
            if (grow < M) {
                float rv = gateS[row * 520 + d]       + bias[d];
                float zv = gateS[row * 520 + 128 + d] + bias[128 + d];
                float xv = gateS[row * 520 + 256 + d] + bias[256 + d];
                float nv = gateS[row * 520 + 384 + d] + bias[384 + d];
                float h  = Hsrc[(size_t)grow * 128 + d];
                float r = 1.f / (1.f + expf(-rv));
                float z = 1.f / (1.f + expf(-zv));
                float n = tanhf(xv + r * nv);
                Hdst[(size_t)grow * 128 + d] = (1.f - z) * n + z * h;
            }
        }
    }
}

// ---------------- FC head: logits = es @ fc_w^T + fc_b ----------------
__global__ __launch_bounds__(256) void fc_kernel(const float* __restrict__ fc_w,
                                                 const float* __restrict__ fc_b,
                                                 float* __restrict__ out) {
    __shared__ float4 Wtile[32 * 32];
    __shared__ float4 xb[8][32];
    int tid = threadIdx.x;
    for (int t = tid; t < 4096; t += 256) {
        int c = t >> 7;
        int k = t & 127;
        ((float*)&Wtile[(k >> 2) * 32 + c])[k & 3] = fc_w[t];
    }
    __syncthreads();
    int w = tid >> 5, lane = tid & 31;
    float bias = fc_b[lane];
    int gw = blockIdx.x * 8 + w;
    int nw = gridDim.x * 8;
    for (int row = gw; row < E_N; row += nw) {
        xb[w][lane] = ((const float4*)g_esb[0])[(size_t)row * 32 + lane];
        __syncwarp();
        float acc = bias;
#pragma unroll
        for (int k4 = 0; k4 < 32; k4++) {
            float4 x  = xb[w][k4];
            float4 wv = Wtile[k4 * 32 + lane];
            acc += x.x * wv.x + x.y * wv.y + x.z * wv.z + x.w * wv.w;
        }
        out[(size_t)row * 32 + lane] = acc;
        __syncwarp();
    }
}

// ---------------- output staging ----------------
__global__ void copy_out_kernel(float4* __restrict__ oes, float4* __restrict__ ops) {
    int t = blockIdx.x * blockDim.x + threadIdx.x;
    const int ne = E_N * 32, np = P_N * 32;
    if (t < ne)            oes[t]      = ((const float4*)g_esb[0])[t];
    else if (t < ne + np)  ops[t - ne] = ((const float4*)g_psb[0])[t - ne];
}

// ---------------- launch ----------------
extern "C" void kernel_launch(void* const* d_in, const int* in_sizes, int n_in,
                              void* d_out, int out_size) {
    const int*   seed  = (const int*)d_in[0];
    const float* es_in = (const float*)d_in[1];
    const float* ps_in = (const float*)d_in[2];
    const int*   erow  = (const int*)d_in[3];
    const int*   ecol  = (const int*)d_in[4];
    const float* eval  = (const float*)d_in[5];
    const float* fc_w  = (const float*)d_in[22];
    const float* fc_b  = (const float*)d_in[23];
    float* out = (float*)d_out;
    const int nseed = in_sizes[0];
    const int nnz   = in_sizes[3];
    const float inv = 1.f / (float)nseed;
    const int smemBytes = ARENA_U32 * 4;

    static int s_attr_done = 0;
    if (!s_attr_done) {
        cudaFuncSetAttribute(gemm_gru_tc, cudaFuncAttributeMaxDynamicSharedMemorySize, smemBytes);
        s_attr_done = 1;
    }

    const int copyThreads = (E_N + P_N) * 32;
    copy_in_kernel<<<(copyThreads + 255) / 256, 256>>>((const float4*)es_in, (const float4*)ps_in);

    for (int l = 0; l < 2; l++)
        for (int pe = 0; pe < 2; pe++) {
            int g = l * 2 + pe;                 // 0=l0_e 1=l0_p 2=l1_e 3=l1_p
            int base = 6 + l * 8 + pe * 4;
            pack_tc_kernel<<<(2 * 384 * 128 + 255) / 256, 256>>>(
                (const float*)d_in[base], (const float*)d_in[base + 1],
                (const float*)d_in[base + 2], (const float*)d_in[base + 3], g);
        }

    for (int l = 0; l < 2; l++) {
        const int src = l;          // l0: read 0 write 1; l1: read 1 write 0
        const int dst = 1 - l;
        zero_msg_kernel<<<(copyThreads + 255) / 256, 256>>>();
        seedsum_kernel<<<nseed, 128>>>(seed, src);
        int spmmThreads = nnz * 8;
        spmm_kernel<<<(spmmThreads + 255) / 256, 256>>>(erow, ecol, eval, nnz, 1, src);
        gemm_gru_tc<<<(P_N + 63) / 64, 256, smemBytes>>>(P_N, l * 2 + 1, 0, src, dst, inv);
        spmm_kernel<<<(spmmThreads + 255) / 256, 256>>>(erow, ecol, eval, nnz, 0, dst);
        gemm_gru_tc<<<(E_N + 63) / 64, 256, smemBytes>>>(E_N, l * 2, 1, src, dst, inv);
    }

    fc_kernel<<<592, 256>>>(fc_w, fc_b, out);
    copy_out_kernel<<<(copyThreads + 255) / 256, 256>>>(
        (float4*)(out + (size_t)E_N * C_N),
        (float4*)(out + (size_t)E_N * C_N + (size_t)E_N * D_N));
}